// round 12
// baseline (speedup 1.0000x reference)
#include <cuda_runtime.h>
#include <cuda_bf16.h>

// MoE noisy top-1 gating, N=262144, D=256, E=3.
//   logits = x@wg + noise * (softplus(x@wn) + 0.2);  out[t] = argmax (as float)
//
// R11: occupancy push. Evidence: issue=45.8% with 4 warps/SMSP all memory-
// blocked ~half the time; occ capped by 128 regs. Cuts:
//  - early token folds (live partials 12 floats, not 24)
//  - 32-bit byte-offset addressing for x
//  - blockDim 128, __launch_bounds__(128,5) -> 102 regs, 20 warps/SM
//  - grid 740 = 148 SM x 5 CTAs, exactly one wave

#define GATE_N 262144
#define GATE_D 256
#define GATE_E 3
#define NOISE_EPS 0.2f

typedef unsigned long long ull;

__device__ __forceinline__ ull pk2(float lo, float hi) {
    ull r;
    asm("mov.b64 %0, {%1, %2};" : "=l"(r) : "f"(lo), "f"(hi));
    return r;
}
__device__ __forceinline__ void fma2(ull& acc, ull a, ull b) {
    asm("fma.rn.f32x2 %0, %1, %2, %0;" : "+l"(acc) : "l"(a), "l"(b));
}
__device__ __forceinline__ float unpk_sum(ull v) {
    float lo, hi;
    asm("mov.b64 {%0, %1}, %2;" : "=f"(lo), "=f"(hi) : "l"(v));
    return lo + hi;
}

// 24 packed FMAs for one token; writes 6 partials.
__device__ __forceinline__ void dot6(const ulonglong2& a, const ulonglong2& b,
                                     const ull (&wgp)[4][3], const ull (&wnp)[4][3],
                                     float (&P)[6]) {
    ull a0 = 0, a1 = 0, a2 = 0, a3 = 0, a4 = 0, a5 = 0;
    const ull xp[4] = {a.x, a.y, b.x, b.y};
#pragma unroll
    for (int p = 0; p < 4; ++p) {
        fma2(a0, xp[p], wgp[p][0]);
        fma2(a1, xp[p], wgp[p][1]);
        fma2(a2, xp[p], wgp[p][2]);
        fma2(a3, xp[p], wnp[p][0]);
        fma2(a4, xp[p], wnp[p][1]);
        fma2(a5, xp[p], wnp[p][2]);
    }
    P[0] = unpk_sum(a0); P[1] = unpk_sum(a1); P[2] = unpk_sum(a2);
    P[3] = unpk_sum(a3); P[4] = unpk_sum(a4); P[5] = unpk_sum(a5);
}

__global__ __launch_bounds__(128, 5)
void moe_gate_kernel(const float* __restrict__ x,
                     const float* __restrict__ wg,
                     const float* __restrict__ wn,
                     const float* __restrict__ noise,
                     float* __restrict__ out)
{
    const int lane   = threadIdx.x & 31;
    const int gwarp  = (blockIdx.x * blockDim.x + threadIdx.x) >> 5;
    const int nwarps = (gridDim.x * blockDim.x) >> 5;
    const int stride = 4 * nwarps;

    // Lane owns dims {4l..4l+3} and {128+4l..128+4l+3} -> 4 f32x2 dim-pairs.
    ull wgp[4][3], wnp[4][3];
#pragma unroll
    for (int p = 0; p < 4; ++p) {
        const int d = (p < 2) ? (4 * lane + 2 * p) : (128 + 4 * lane + 2 * (p - 2));
#pragma unroll
        for (int e = 0; e < 3; ++e) {
            wgp[p][e] = pk2(__ldg(wg + d * 3 + e), __ldg(wg + (d + 1) * 3 + e));
            wnp[p][e] = pk2(__ldg(wn + d * 3 + e), __ldg(wn + (d + 1) * 3 + e));
        }
    }

    // 32-bit byte offsets: row = 1024B; lane reads +16*lane and +512+16*lane.
    const char* __restrict__ xb8 = (const char*)x;
    const unsigned offA = 16u * lane;
    const unsigned offB = 512u + 16u * lane;

    const int quad  = lane >> 3;   // token this lane finalizes
    const int j     = lane & 7;    // role in quadrant (j<3 -> expert j)
    const int qbase = lane & 24;   // first lane of my quadrant

    int t0 = 4 * gwarp;
    if (t0 >= GATE_N) return;

    // ---- prologue loads ----
    ulonglong2 xa[4], xb[4];
#pragma unroll
    for (int q = 0; q < 4; ++q) {
        const unsigned row = (unsigned)(t0 + q) << 10;   // *1024 bytes
        xa[q] = *(const ulonglong2*)(xb8 + row + offA);
        xb[q] = *(const ulonglong2*)(xb8 + row + offB);
    }
    float nsraw = (lane < 12) ? __ldg(noise + (size_t)t0 * 3 + lane) : 0.f;

    const bool lo16 = (lane < 16);
    const bool lo8  = ((lane & 8) == 0);

    while (t0 < GATE_N) {
        const int tn = t0 + stride;
        const bool more = (tn < GATE_N);

        // ---- tokens 0 & 2, then fold -> U (partials die early) ----
        float U[6];
        {
            float P0[6], P2[6];
            dot6(xa[0], xb[0], wgp, wnp, P0);
            if (more) {
                const unsigned row = (unsigned)tn << 10;
                xa[0] = *(const ulonglong2*)(xb8 + row + offA);
                xb[0] = *(const ulonglong2*)(xb8 + row + offB);
            }
            dot6(xa[2], xb[2], wgp, wnp, P2);
            if (more) {
                const unsigned row = (unsigned)(tn + 2) << 10;
                xa[2] = *(const ulonglong2*)(xb8 + row + offA);
                xb[2] = *(const ulonglong2*)(xb8 + row + offB);
            }
#pragma unroll
            for (int e = 0; e < 6; ++e) {
                const float u  = lo16 ? P0[e] : P2[e];
                const float uv = lo16 ? P2[e] : P0[e];
                U[e] = u + __shfl_xor_sync(0xFFFFFFFFu, uv, 16);
            }
        }

        // ---- tokens 1 & 3, then fold -> W ----
        float W[6];
        {
            float P1[6], P3[6];
            dot6(xa[1], xb[1], wgp, wnp, P1);
            if (more) {
                const unsigned row = (unsigned)(tn + 1) << 10;
                xa[1] = *(const ulonglong2*)(xb8 + row + offA);
                xb[1] = *(const ulonglong2*)(xb8 + row + offB);
            }
            dot6(xa[3], xb[3], wgp, wnp, P3);
            if (more) {
                const unsigned row = (unsigned)(tn + 3) << 10;
                xa[3] = *(const ulonglong2*)(xb8 + row + offA);
                xb[3] = *(const ulonglong2*)(xb8 + row + offB);
            }
#pragma unroll
            for (int e = 0; e < 6; ++e) {
                const float w  = lo16 ? P1[e] : P3[e];
                const float wv = lo16 ? P3[e] : P1[e];
                W[e] = w + __shfl_xor_sync(0xFFFFFFFFu, wv, 16);
            }
        }

        // ---- noise prefetch ----
        float nsn = 0.f;
        if (more && lane < 12) nsn = __ldg(noise + (size_t)tn * 3 + lane);

        // ---- fold round 2 (xor 8): quadrant q holds token q ----
        float R[6];
#pragma unroll
        for (int e = 0; e < 6; ++e) {
            const float r  = lo8 ? U[e] : W[e];
            const float rv = lo8 ? W[e] : U[e];
            R[e] = r + __shfl_xor_sync(0xFFFFFFFFu, rv, 8);
        }

        // ---- butterfly within 8-lane quadrants ----
#pragma unroll
        for (int off = 4; off > 0; off >>= 1) {
#pragma unroll
            for (int e = 0; e < 6; ++e)
                R[e] += __shfl_xor_sync(0xFFFFFFFFu, R[e], off);
        }

        // ---- tail: lane 8q+j (j<3) owns expert j of token q ----
        const float nv = __shfl_sync(0xFFFFFFFFu, nsraw, 3 * quad + j);
        const float cg = (j == 1) ? R[1] : ((j == 2) ? R[2] : R[0]);
        const float cn = (j == 1) ? R[4] : ((j == 2) ? R[5] : R[3]);
        const float sp = fmaxf(cn, 0.f) + log1pf(expf(-fabsf(cn)));
        const float logit = fmaf(nv, sp + NOISE_EPS, cg);

        const float l1 = __shfl_sync(0xFFFFFFFFu, logit, qbase + 1);
        const float l2 = __shfl_sync(0xFFFFFFFFu, logit, qbase + 2);

        if (j == 0) {
            int   idx  = 0;
            float best = logit;          // expert 0
            if (l1 > best) { best = l1; idx = 1; }
            if (l2 > best) {            idx = 2; }
            out[t0 + quad] = (float)idx; // 4 lanes, 16B coalesced
        }

        // ---- rotate ----
        nsraw = nsn;
        t0 = tn;
    }
}

extern "C" void kernel_launch(void* const* d_in, const int* in_sizes, int n_in,
                              void* d_out, int out_size)
{
    // Resolve inputs BY SIZE (robust to metadata ordering).
    //   N*D -> input, N*E -> noise, D*E -> w_gate (first), w_noise (second)
    const float* x   = nullptr;
    const float* wg  = nullptr;
    const float* wn  = nullptr;
    const float* nse = nullptr;

    for (int i = 0; i < n_in; ++i) {
        const long long sz = in_sizes[i];
        if (sz == (long long)GATE_N * GATE_D) {
            x = (const float*)d_in[i];
        } else if (sz == (long long)GATE_N * GATE_E) {
            nse = (const float*)d_in[i];
        } else if (sz == (long long)GATE_D * GATE_E) {
            if (!wg) wg = (const float*)d_in[i];
            else     wn = (const float*)d_in[i];
        }
    }

    float* out = (float*)d_out;
    (void)out_size;

    // 740 blocks x 128 threads: 5 CTAs/SM on 148 SMs, exactly one wave.
    moe_gate_kernel<<<740, 128>>>(x, wg, wn, nse, out);
}

// round 13
// speedup vs baseline: 1.3871x; 1.3871x over previous
#include <cuda_runtime.h>
#include <cuda_bf16.h>
#include <cuda_pipeline.h>

// MoE noisy top-1 gating, N=262144, D=256, E=3.
//   logits = x@wg + noise * (softplus(x@wn) + 0.2);  out[t] = argmax (as float)
//
// R12: R8 compute structure (batched loads, late folds — the 47.6us winner)
// with cp.async (LDGSTS) depth-3 smem staging. Loads have no register
// destination, so ~12KB/warp stays in flight continuously regardless of
// compute phase. Per-lane copies == per-lane reads (no cross-lane sync).

#define GATE_N 262144
#define GATE_D 256
#define GATE_E 3
#define NOISE_EPS 0.2f
#define DEPTH 3

typedef unsigned long long ull;

__device__ __forceinline__ ull pk2(float lo, float hi) {
    ull r;
    asm("mov.b64 %0, {%1, %2};" : "=l"(r) : "f"(lo), "f"(hi));
    return r;
}
__device__ __forceinline__ void fma2(ull& acc, ull a, ull b) {
    asm("fma.rn.f32x2 %0, %1, %2, %0;" : "+l"(acc) : "l"(a), "l"(b));
}
__device__ __forceinline__ float unpk_sum(ull v) {
    float lo, hi;
    asm("mov.b64 {%0, %1}, %2;" : "=f"(lo), "=f"(hi) : "l"(v));
    return lo + hi;
}

// Stage one 4-token tile (4KB) into this warp's smem buffer via cp.async.
// Lane l copies exactly the bytes lane l later reads.
__device__ __forceinline__ void stage_tile(char* wbuf, const char* xb8,
                                           int t, int lane, bool valid) {
    if (valid) {
        const unsigned lo = 16u * lane;
#pragma unroll
        for (int q = 0; q < 4; ++q) {
            const char* src = xb8 + ((size_t)(t + q) << 10);
            char* dst = wbuf + (q << 10);
            __pipeline_memcpy_async(dst + lo,        src + lo,        16);
            __pipeline_memcpy_async(dst + 512 + lo,  src + 512 + lo,  16);
        }
    }
    __pipeline_commit();   // always commit: uniform group counting
}

__global__ __launch_bounds__(256, 2)
void moe_gate_kernel(const float* __restrict__ x,
                     const float* __restrict__ wg,
                     const float* __restrict__ wn,
                     const float* __restrict__ noise,
                     float* __restrict__ out)
{
    extern __shared__ char smem[];   // 8 warps x DEPTH x 4KB

    const int lane   = threadIdx.x & 31;
    const int wid    = threadIdx.x >> 5;
    const int gwarp  = (blockIdx.x * blockDim.x + threadIdx.x) >> 5;
    const int nwarps = (gridDim.x * blockDim.x) >> 5;
    const int stride = 4 * nwarps;

    // Lane owns dims {4l..4l+3} and {128+4l..128+4l+3} -> 4 f32x2 dim-pairs.
    ull wgp[4][3], wnp[4][3];
#pragma unroll
    for (int p = 0; p < 4; ++p) {
        const int d = (p < 2) ? (4 * lane + 2 * p) : (128 + 4 * lane + 2 * (p - 2));
#pragma unroll
        for (int e = 0; e < 3; ++e) {
            wgp[p][e] = pk2(__ldg(wg + d * 3 + e), __ldg(wg + (d + 1) * 3 + e));
            wnp[p][e] = pk2(__ldg(wn + d * 3 + e), __ldg(wn + (d + 1) * 3 + e));
        }
    }

    const char* xb8 = (const char*)x;
    char* wbase = smem + (size_t)wid * DEPTH * 4096;

    const int quad  = lane >> 3;   // token this lane finalizes
    const int j     = lane & 7;    // role in quadrant (j<3 -> expert j)
    const int qbase = lane & 24;   // first lane of my quadrant
    const bool lo16 = (lane < 16);
    const bool lo8  = ((lane & 8) == 0);
    const unsigned loff = 16u * lane;

    int t0 = 4 * gwarp;
    if (t0 >= GATE_N) return;

    // ---- prime the pipeline: DEPTH tiles ----
#pragma unroll
    for (int k = 0; k < DEPTH; ++k) {
        const int tk = t0 + k * stride;
        stage_tile(wbase + k * 4096, xb8, tk, lane, tk < GATE_N);
    }
    float nsraw = (lane < 12) ? __ldg(noise + (size_t)t0 * 3 + lane) : 0.f;

    int s = 0;
    while (t0 < GATE_N) {
        const int tn   = t0 + stride;
        const int tpre = t0 + DEPTH * stride;

        // ---- oldest staged tile is ready ----
        __pipeline_wait_prior(DEPTH - 1);

        // pull tile into registers (8x LDS.128)
        const char* wbuf = wbase + s * 4096;
        ulonglong2 xa[4], xb[4];
#pragma unroll
        for (int q = 0; q < 4; ++q) {
            xa[q] = *(const ulonglong2*)(wbuf + (q << 10) + loff);
            xb[q] = *(const ulonglong2*)(wbuf + (q << 10) + 512 + loff);
        }

        // refill this slot for tile t0 + DEPTH*stride (async, no registers)
        stage_tile(wbase + s * 4096, xb8, tpre, lane, tpre < GATE_N);

        // noise prefetch for next iteration
        float nsn = 0.f;
        if (tn < GATE_N && lane < 12) nsn = __ldg(noise + (size_t)tn * 3 + lane);

        // ---- FMA phase: 24 fma2 per token ----
        float P[4][6];
#pragma unroll
        for (int q = 0; q < 4; ++q) {
            ull a0 = 0, a1 = 0, a2 = 0, a3 = 0, a4 = 0, a5 = 0;
            const ull xp[4] = {xa[q].x, xa[q].y, xb[q].x, xb[q].y};
#pragma unroll
            for (int p = 0; p < 4; ++p) {
                fma2(a0, xp[p], wgp[p][0]);
                fma2(a1, xp[p], wgp[p][1]);
                fma2(a2, xp[p], wgp[p][2]);
                fma2(a3, xp[p], wnp[p][0]);
                fma2(a4, xp[p], wnp[p][1]);
                fma2(a5, xp[p], wnp[p][2]);
            }
            P[q][0] = unpk_sum(a0); P[q][1] = unpk_sum(a1); P[q][2] = unpk_sum(a2);
            P[q][3] = unpk_sum(a3); P[q][4] = unpk_sum(a4); P[q][5] = unpk_sum(a5);
        }

        // ---- fold round 1 (xor 16): T0<->T2, T1<->T3 ----
        float U[6], W[6];
#pragma unroll
        for (int e = 0; e < 6; ++e) {
            const float u  = lo16 ? P[0][e] : P[2][e];
            const float uv = lo16 ? P[2][e] : P[0][e];
            U[e] = u + __shfl_xor_sync(0xFFFFFFFFu, uv, 16);
            const float w  = lo16 ? P[1][e] : P[3][e];
            const float wv = lo16 ? P[3][e] : P[1][e];
            W[e] = w + __shfl_xor_sync(0xFFFFFFFFu, wv, 16);
        }

        // ---- fold round 2 (xor 8): quadrant q holds token q ----
        float R[6];
#pragma unroll
        for (int e = 0; e < 6; ++e) {
            const float r  = lo8 ? U[e] : W[e];
            const float rv = lo8 ? W[e] : U[e];
            R[e] = r + __shfl_xor_sync(0xFFFFFFFFu, rv, 8);
        }

        // ---- butterfly within 8-lane quadrants ----
#pragma unroll
        for (int off = 4; off > 0; off >>= 1) {
#pragma unroll
            for (int e = 0; e < 6; ++e)
                R[e] += __shfl_xor_sync(0xFFFFFFFFu, R[e], off);
        }

        // ---- tail: lane 8q+j (j<3) owns expert j of token q ----
        const float nv = __shfl_sync(0xFFFFFFFFu, nsraw, 3 * quad + j);
        const float cg = (j == 1) ? R[1] : ((j == 2) ? R[2] : R[0]);
        const float cn = (j == 1) ? R[4] : ((j == 2) ? R[5] : R[3]);
        const float sp = fmaxf(cn, 0.f) + log1pf(expf(-fabsf(cn)));
        const float logit = fmaf(nv, sp + NOISE_EPS, cg);

        const float l1 = __shfl_sync(0xFFFFFFFFu, logit, qbase + 1);
        const float l2 = __shfl_sync(0xFFFFFFFFu, logit, qbase + 2);

        if (j == 0) {
            int   idx  = 0;
            float best = logit;          // expert 0
            if (l1 > best) { best = l1; idx = 1; }
            if (l2 > best) {            idx = 2; }
            out[t0 + quad] = (float)idx; // 4 lanes, 16B coalesced
        }

        // ---- rotate ----
        nsraw = nsn;
        t0 = tn;
        s = (s + 1 == DEPTH) ? 0 : (s + 1);
    }
}

extern "C" void kernel_launch(void* const* d_in, const int* in_sizes, int n_in,
                              void* d_out, int out_size)
{
    // Resolve inputs BY SIZE (robust to metadata ordering).
    //   N*D -> input, N*E -> noise, D*E -> w_gate (first), w_noise (second)
    const float* x   = nullptr;
    const float* wg  = nullptr;
    const float* wn  = nullptr;
    const float* nse = nullptr;

    for (int i = 0; i < n_in; ++i) {
        const long long sz = in_sizes[i];
        if (sz == (long long)GATE_N * GATE_D) {
            x = (const float*)d_in[i];
        } else if (sz == (long long)GATE_N * GATE_E) {
            nse = (const float*)d_in[i];
        } else if (sz == (long long)GATE_D * GATE_E) {
            if (!wg) wg = (const float*)d_in[i];
            else     wn = (const float*)d_in[i];
        }
    }

    float* out = (float*)d_out;
    (void)out_size;

    const int smem_bytes = 8 * DEPTH * 4096;   // 96KB per CTA
    static bool attr_set = false;
    if (!attr_set) {
        cudaFuncSetAttribute(moe_gate_kernel,
                             cudaFuncAttributeMaxDynamicSharedMemorySize,
                             smem_bytes);
        attr_set = true;
    }

    moe_gate_kernel<<<592, 256, smem_bytes>>>(x, wg, wn, nse, out);
}

// round 14
// speedup vs baseline: 1.4259x; 1.0280x over previous
#include <cuda_runtime.h>
#include <cuda_bf16.h>
#include <cuda_pipeline.h>

// MoE noisy top-1 gating, N=262144, D=256, E=3.
//   logits = x@wg + noise * (softplus(x@wn) + 0.2);  out[t] = argmax (as float)
//
// R13: cp.async staging decouples DRAM traffic from compute structure, so we
// can take R11's register cuts (early folds, LDS-on-demand x) WITHOUT killing
// DRAM MLP, and spend the registers on occupancy: 128 thr x 5 CTAs/SM =
// 20 warps/SM (+25% vs R8/R12's 16). Grid 740 = 148x5, exactly one wave.

#define GATE_N 262144
#define GATE_D 256
#define GATE_E 3
#define NOISE_EPS 0.2f
#define DEPTH 2
#define WARPS_PER_CTA 4

typedef unsigned long long ull;

__device__ __forceinline__ ull pk2(float lo, float hi) {
    ull r;
    asm("mov.b64 %0, {%1, %2};" : "=l"(r) : "f"(lo), "f"(hi));
    return r;
}
__device__ __forceinline__ void fma2(ull& acc, ull a, ull b) {
    asm("fma.rn.f32x2 %0, %1, %2, %0;" : "+l"(acc) : "l"(a), "l"(b));
}
__device__ __forceinline__ float unpk_sum(ull v) {
    float lo, hi;
    asm("mov.b64 {%0, %1}, %2;" : "=f"(lo), "=f"(hi) : "l"(v));
    return lo + hi;
}

// Stage one 4-token tile (4KB) into this warp's smem slot via cp.async.
// Lane l copies exactly the bytes lane l later reads.
__device__ __forceinline__ void stage_tile(char* wbuf, const char* xb8,
                                           int t, int lane, bool valid) {
    if (valid) {
        const unsigned lo = 16u * lane;
#pragma unroll
        for (int q = 0; q < 4; ++q) {
            const char* src = xb8 + ((size_t)(t + q) << 10);
            char* dst = wbuf + (q << 10);
            __pipeline_memcpy_async(dst + lo,       src + lo,       16);
            __pipeline_memcpy_async(dst + 512 + lo, src + 512 + lo, 16);
        }
    }
    __pipeline_commit();   // always commit: uniform group counting
}

// 24 packed FMAs for one token (x read from smem slot); writes 6 partials.
__device__ __forceinline__ void dot6_s(const char* wbuf, int q, unsigned loff,
                                       const ull (&wgp)[4][3], const ull (&wnp)[4][3],
                                       float (&P)[6]) {
    const ulonglong2 a = *(const ulonglong2*)(wbuf + (q << 10) + loff);
    const ulonglong2 b = *(const ulonglong2*)(wbuf + (q << 10) + 512 + loff);
    ull a0 = 0, a1 = 0, a2 = 0, a3 = 0, a4 = 0, a5 = 0;
    const ull xp[4] = {a.x, a.y, b.x, b.y};
#pragma unroll
    for (int p = 0; p < 4; ++p) {
        fma2(a0, xp[p], wgp[p][0]);
        fma2(a1, xp[p], wgp[p][1]);
        fma2(a2, xp[p], wgp[p][2]);
        fma2(a3, xp[p], wnp[p][0]);
        fma2(a4, xp[p], wnp[p][1]);
        fma2(a5, xp[p], wnp[p][2]);
    }
    P[0] = unpk_sum(a0); P[1] = unpk_sum(a1); P[2] = unpk_sum(a2);
    P[3] = unpk_sum(a3); P[4] = unpk_sum(a4); P[5] = unpk_sum(a5);
}

__global__ __launch_bounds__(128, 5)
void moe_gate_kernel(const float* __restrict__ x,
                     const float* __restrict__ wg,
                     const float* __restrict__ wn,
                     const float* __restrict__ noise,
                     float* __restrict__ out)
{
    extern __shared__ char smem[];   // 4 warps x DEPTH x 4KB = 32KB

    const int lane   = threadIdx.x & 31;
    const int wid    = threadIdx.x >> 5;
    const int gwarp  = (blockIdx.x * blockDim.x + threadIdx.x) >> 5;
    const int nwarps = (gridDim.x * blockDim.x) >> 5;
    const int stride = 4 * nwarps;

    // Lane owns dims {4l..4l+3} and {128+4l..128+4l+3} -> 4 f32x2 dim-pairs.
    ull wgp[4][3], wnp[4][3];
#pragma unroll
    for (int p = 0; p < 4; ++p) {
        const int d = (p < 2) ? (4 * lane + 2 * p) : (128 + 4 * lane + 2 * (p - 2));
#pragma unroll
        for (int e = 0; e < 3; ++e) {
            wgp[p][e] = pk2(__ldg(wg + d * 3 + e), __ldg(wg + (d + 1) * 3 + e));
            wnp[p][e] = pk2(__ldg(wn + d * 3 + e), __ldg(wn + (d + 1) * 3 + e));
        }
    }

    const char* xb8 = (const char*)x;
    char* wbase = smem + (size_t)wid * DEPTH * 4096;

    const int quad  = lane >> 3;   // token this lane finalizes
    const int j     = lane & 7;    // role in quadrant (j<3 -> expert j)
    const int qbase = lane & 24;   // first lane of my quadrant
    const bool lo16 = (lane < 16);
    const bool lo8  = ((lane & 8) == 0);
    const unsigned loff = 16u * lane;

    int t0 = 4 * gwarp;
    if (t0 >= GATE_N) return;

    // ---- prime the pipeline: DEPTH tiles ----
#pragma unroll
    for (int k = 0; k < DEPTH; ++k) {
        const int tk = t0 + k * stride;
        stage_tile(wbase + k * 4096, xb8, tk, lane, tk < GATE_N);
    }
    float nsraw = (lane < 12) ? __ldg(noise + (size_t)t0 * 3 + lane) : 0.f;

    int s = 0;
    while (t0 < GATE_N) {
        const int tn   = t0 + stride;
        const int tpre = t0 + DEPTH * stride;

        // ---- oldest staged tile ready ----
        __pipeline_wait_prior(DEPTH - 1);
        const char* wbuf = wbase + s * 4096;

        // ---- tokens 0 & 2, fold -> U (partials die early) ----
        float U[6];
        {
            float P0[6], P2[6];
            dot6_s(wbuf, 0, loff, wgp, wnp, P0);
            dot6_s(wbuf, 2, loff, wgp, wnp, P2);
#pragma unroll
            for (int e = 0; e < 6; ++e) {
                const float u  = lo16 ? P0[e] : P2[e];
                const float uv = lo16 ? P2[e] : P0[e];
                U[e] = u + __shfl_xor_sync(0xFFFFFFFFu, uv, 16);
            }
        }

        // ---- tokens 1 & 3, fold -> W ----
        float W[6];
        {
            float P1[6], P3[6];
            dot6_s(wbuf, 1, loff, wgp, wnp, P1);
            dot6_s(wbuf, 3, loff, wgp, wnp, P3);
#pragma unroll
            for (int e = 0; e < 6; ++e) {
                const float w  = lo16 ? P1[e] : P3[e];
                const float wv = lo16 ? P3[e] : P1[e];
                W[e] = w + __shfl_xor_sync(0xFFFFFFFFu, wv, 16);
            }
        }

        // ---- all LDS of slot s done -> refill it (async, no registers) ----
        stage_tile(wbase + s * 4096, xb8, tpre, lane, tpre < GATE_N);

        // noise prefetch for next iteration
        float nsn = 0.f;
        if (tn < GATE_N && lane < 12) nsn = __ldg(noise + (size_t)tn * 3 + lane);

        // ---- fold round 2 (xor 8): quadrant q holds token q ----
        float R[6];
#pragma unroll
        for (int e = 0; e < 6; ++e) {
            const float r  = lo8 ? U[e] : W[e];
            const float rv = lo8 ? W[e] : U[e];
            R[e] = r + __shfl_xor_sync(0xFFFFFFFFu, rv, 8);
        }

        // ---- butterfly within 8-lane quadrants ----
#pragma unroll
        for (int off = 4; off > 0; off >>= 1) {
#pragma unroll
            for (int e = 0; e < 6; ++e)
                R[e] += __shfl_xor_sync(0xFFFFFFFFu, R[e], off);
        }

        // ---- tail: lane 8q+j (j<3) owns expert j of token q ----
        const float nv = __shfl_sync(0xFFFFFFFFu, nsraw, 3 * quad + j);
        const float cg = (j == 1) ? R[1] : ((j == 2) ? R[2] : R[0]);
        const float cn = (j == 1) ? R[4] : ((j == 2) ? R[5] : R[3]);
        const float sp = fmaxf(cn, 0.f) + log1pf(expf(-fabsf(cn)));
        const float logit = fmaf(nv, sp + NOISE_EPS, cg);

        const float l1 = __shfl_sync(0xFFFFFFFFu, logit, qbase + 1);
        const float l2 = __shfl_sync(0xFFFFFFFFu, logit, qbase + 2);

        if (j == 0) {
            int   idx  = 0;
            float best = logit;          // expert 0
            if (l1 > best) { best = l1; idx = 1; }
            if (l2 > best) {            idx = 2; }
            out[t0 + quad] = (float)idx; // 4 lanes, 16B coalesced
        }

        // ---- rotate ----
        nsraw = nsn;
        t0 = tn;
        s ^= 1;   // DEPTH == 2
    }
}

extern "C" void kernel_launch(void* const* d_in, const int* in_sizes, int n_in,
                              void* d_out, int out_size)
{
    // Resolve inputs BY SIZE (robust to metadata ordering).
    //   N*D -> input, N*E -> noise, D*E -> w_gate (first), w_noise (second)
    const float* x   = nullptr;
    const float* wg  = nullptr;
    const float* wn  = nullptr;
    const float* nse = nullptr;

    for (int i = 0; i < n_in; ++i) {
        const long long sz = in_sizes[i];
        if (sz == (long long)GATE_N * GATE_D) {
            x = (const float*)d_in[i];
        } else if (sz == (long long)GATE_N * GATE_E) {
            nse = (const float*)d_in[i];
        } else if (sz == (long long)GATE_D * GATE_E) {
            if (!wg) wg = (const float*)d_in[i];
            else     wn = (const float*)d_in[i];
        }
    }

    float* out = (float*)d_out;
    (void)out_size;

    const int smem_bytes = WARPS_PER_CTA * DEPTH * 4096;   // 32KB per CTA
    // 740 = 148 SMs x 5 CTAs: exactly one wave at occupancy 5.
    moe_gate_kernel<<<740, 128, smem_bytes>>>(x, wg, wn, nse, out);
}

// round 15
// speedup vs baseline: 1.4738x; 1.0336x over previous
#include <cuda_runtime.h>
#include <cuda_bf16.h>

// MoE noisy top-1 gating, N=262144, D=256, E=3.
//   logits = x@wg + noise * (softplus(x@wn) + 0.2);  out[t] = argmax (as float)
//
// R14: R8 compute structure (best verified: 47.6us, DRAM 75%) with a SINGLE
// persistent wave: 296 blocks = 148 SMs x 2 resident CTAs. Removes the
// wave-2 transition + duplicate prologue + tail imbalance that R8's 592-block
// launch paid. Evidence: 4 designs converge at ~5.9TB/s -> DRAM rate is the
// ceiling; only the non-DRAM overhead (~2.5us) is recoverable.

#define GATE_N 262144
#define GATE_D 256
#define GATE_E 3
#define NOISE_EPS 0.2f

typedef unsigned long long ull;

__device__ __forceinline__ ull pk2(float lo, float hi) {
    ull r;
    asm("mov.b64 %0, {%1, %2};" : "=l"(r) : "f"(lo), "f"(hi));
    return r;
}
__device__ __forceinline__ void fma2(ull& acc, ull a, ull b) {
    asm("fma.rn.f32x2 %0, %1, %2, %0;" : "+l"(acc) : "l"(a), "l"(b));
}
__device__ __forceinline__ float unpk_sum(ull v) {
    float lo, hi;
    asm("mov.b64 {%0, %1}, %2;" : "=f"(lo), "=f"(hi) : "l"(v));
    return lo + hi;
}

__global__ __launch_bounds__(256, 2)
void moe_gate_kernel(const float* __restrict__ x,
                     const float* __restrict__ wg,
                     const float* __restrict__ wn,
                     const float* __restrict__ noise,
                     float* __restrict__ out)
{
    const int lane   = threadIdx.x & 31;
    const int gwarp  = (blockIdx.x * blockDim.x + threadIdx.x) >> 5;
    const int nwarps = (gridDim.x * blockDim.x) >> 5;
    const int stride = 4 * nwarps;

    // Lane owns dims {4l..4l+3} and {128+4l..128+4l+3} -> 4 f32x2 dim-pairs.
    ull wgp[4][3], wnp[4][3];
#pragma unroll
    for (int p = 0; p < 4; ++p) {
        const int d = (p < 2) ? (4 * lane + 2 * p) : (128 + 4 * lane + 2 * (p - 2));
#pragma unroll
        for (int e = 0; e < 3; ++e) {
            wgp[p][e] = pk2(__ldg(wg + d * 3 + e), __ldg(wg + (d + 1) * 3 + e));
            wnp[p][e] = pk2(__ldg(wn + d * 3 + e), __ldg(wn + (d + 1) * 3 + e));
        }
    }

    // Row = 256 floats = 64 ulonglong2. Lane reads idx lane and 32+lane.
    const ulonglong2* __restrict__ x2 = reinterpret_cast<const ulonglong2*>(x);

    const int quad  = lane >> 3;   // token this lane finalizes
    const int j     = lane & 7;    // role in quadrant (j<3 -> expert j)
    const int qbase = lane & 24;   // first lane of my quadrant
    const bool lo16 = (lane < 16);
    const bool lo8  = ((lane & 8) == 0);

    int t0 = 4 * gwarp;
    if (t0 >= GATE_N) return;

    // ---- prologue loads ----
    ulonglong2 xa[4], xb[4];
#pragma unroll
    for (int q = 0; q < 4; ++q) {
        xa[q] = x2[(size_t)(t0 + q) * 64 + lane];
        xb[q] = x2[(size_t)(t0 + q) * 64 + 32 + lane];
    }
    float nsraw = (lane < 12) ? __ldg(noise + (size_t)t0 * 3 + lane) : 0.f;

    while (t0 < GATE_N) {
        const int tn = t0 + stride;

        // ---- FMA phase: per token 24 fma2, then unpack (acc stays small) ----
        float P[4][6];
#pragma unroll
        for (int q = 0; q < 4; ++q) {
            ull a0 = 0, a1 = 0, a2 = 0, a3 = 0, a4 = 0, a5 = 0;
            const ull xp[4] = {xa[q].x, xa[q].y, xb[q].x, xb[q].y};
#pragma unroll
            for (int p = 0; p < 4; ++p) {
                fma2(a0, xp[p], wgp[p][0]);
                fma2(a1, xp[p], wgp[p][1]);
                fma2(a2, xp[p], wgp[p][2]);
                fma2(a3, xp[p], wnp[p][0]);
                fma2(a4, xp[p], wnp[p][1]);
                fma2(a5, xp[p], wnp[p][2]);
            }
            P[q][0] = unpk_sum(a0); P[q][1] = unpk_sum(a1); P[q][2] = unpk_sum(a2);
            P[q][3] = unpk_sum(a3); P[q][4] = unpk_sum(a4); P[q][5] = unpk_sum(a5);
        }

        // ---- prefetch next iteration (overlaps reduction + tail) ----
        float nsn = 0.f;
        if (tn < GATE_N) {
#pragma unroll
            for (int q = 0; q < 4; ++q) {
                xa[q] = x2[(size_t)(tn + q) * 64 + lane];
                xb[q] = x2[(size_t)(tn + q) * 64 + 32 + lane];
            }
            if (lane < 12) nsn = __ldg(noise + (size_t)tn * 3 + lane);
        }

        // ---- fold round 1 (xor 16): T0<->T2, T1<->T3 ----
        float U[6], W[6];
#pragma unroll
        for (int e = 0; e < 6; ++e) {
            const float u  = lo16 ? P[0][e] : P[2][e];
            const float uv = lo16 ? P[2][e] : P[0][e];
            U[e] = u + __shfl_xor_sync(0xFFFFFFFFu, uv, 16);
            const float w  = lo16 ? P[1][e] : P[3][e];
            const float wv = lo16 ? P[3][e] : P[1][e];
            W[e] = w + __shfl_xor_sync(0xFFFFFFFFu, wv, 16);
        }

        // ---- fold round 2 (xor 8): quadrant q holds token q ----
        float R[6];
#pragma unroll
        for (int e = 0; e < 6; ++e) {
            const float r  = lo8 ? U[e] : W[e];
            const float rv = lo8 ? W[e] : U[e];
            R[e] = r + __shfl_xor_sync(0xFFFFFFFFu, rv, 8);
        }

        // ---- butterfly within 8-lane quadrants ----
#pragma unroll
        for (int off = 4; off > 0; off >>= 1) {
#pragma unroll
            for (int e = 0; e < 6; ++e)
                R[e] += __shfl_xor_sync(0xFFFFFFFFu, R[e], off);
        }

        // ---- tail: lane 8q+j (j<3) owns expert j of token q ----
        const float nv = __shfl_sync(0xFFFFFFFFu, nsraw, 3 * quad + j);
        const float cg = (j == 1) ? R[1] : ((j == 2) ? R[2] : R[0]);
        const float cn = (j == 1) ? R[4] : ((j == 2) ? R[5] : R[3]);
        const float sp = fmaxf(cn, 0.f) + log1pf(expf(-fabsf(cn)));
        const float logit = fmaf(nv, sp + NOISE_EPS, cg);

        const float l1 = __shfl_sync(0xFFFFFFFFu, logit, qbase + 1);
        const float l2 = __shfl_sync(0xFFFFFFFFu, logit, qbase + 2);

        if (j == 0) {
            int   idx  = 0;
            float best = logit;          // expert 0
            if (l1 > best) { best = l1; idx = 1; }
            if (l2 > best) {            idx = 2; }
            out[t0 + quad] = (float)idx; // 4 lanes, 16B coalesced
        }

        // ---- rotate pipeline ----
        nsraw = nsn;
        t0 = tn;
    }
}

extern "C" void kernel_launch(void* const* d_in, const int* in_sizes, int n_in,
                              void* d_out, int out_size)
{
    // Resolve inputs BY SIZE (robust to metadata ordering).
    //   N*D -> input, N*E -> noise, D*E -> w_gate (first), w_noise (second)
    const float* x   = nullptr;
    const float* wg  = nullptr;
    const float* wn  = nullptr;
    const float* nse = nullptr;

    for (int i = 0; i < n_in; ++i) {
        const long long sz = in_sizes[i];
        if (sz == (long long)GATE_N * GATE_D) {
            x = (const float*)d_in[i];
        } else if (sz == (long long)GATE_N * GATE_E) {
            nse = (const float*)d_in[i];
        } else if (sz == (long long)GATE_D * GATE_E) {
            if (!wg) wg = (const float*)d_in[i];
            else     wn = (const float*)d_in[i];
        }
    }

    float* out = (float*)d_out;
    (void)out_size;

    // 296 blocks = 148 SMs x 2 resident CTAs: ONE persistent wave,
    // grid-stride gives each warp ~28 tiles (balanced +/-1).
    moe_gate_kernel<<<296, 256>>>(x, wg, wn, nse, out);
}

// round 17
// speedup vs baseline: 1.4748x; 1.0007x over previous
#include <cuda_runtime.h>
#include <cuda_bf16.h>

// MoE noisy top-1 gating, N=262144, D=256, E=3.
//   logits = x@wg + noise * (softplus(x@wn) + 0.2);  out[t] = argmax (as float)
//
// R16: 256-bit streaming loads. ptxas: L2::evict_first is only encodable on
// .v8.b32/.v4.b64 (32B) loads -> restructure lane ownership to 8 CONTIGUOUS
// dims {8l..8l+7}: one LDG.256 per token per lane covers the whole 1024B row
// warp-wide. Halves x-load instruction count vs LDG.128 pairs; enables
// L1::no_allocate.L2::evict_first on the read-once stream. Registers, FMA
// count, reduction tree, and tail numerics unchanged from the 47.6us base.

#define GATE_N 262144
#define GATE_D 256
#define GATE_E 3
#define NOISE_EPS 0.2f

typedef unsigned long long ull;

struct u64x4 { ull a, b, c, d; };

__device__ __forceinline__ ull pk2(float lo, float hi) {
    ull r;
    asm("mov.b64 %0, {%1, %2};" : "=l"(r) : "f"(lo), "f"(hi));
    return r;
}
__device__ __forceinline__ void fma2(ull& acc, ull a, ull b) {
    asm("fma.rn.f32x2 %0, %1, %2, %0;" : "+l"(acc) : "l"(a), "l"(b));
}
__device__ __forceinline__ float unpk_sum(ull v) {
    float lo, hi;
    asm("mov.b64 {%0, %1}, %2;" : "=f"(lo), "=f"(hi) : "l"(v));
    return lo + hi;
}
// 32B streaming load: read-once data, no L1 allocate, L2 evict-first.
__device__ __forceinline__ u64x4 ldg_stream256(const void* p) {
    u64x4 v;
    asm volatile("ld.global.nc.L1::no_allocate.L2::evict_first.v4.b64 "
                 "{%0, %1, %2, %3}, [%4];"
                 : "=l"(v.a), "=l"(v.b), "=l"(v.c), "=l"(v.d) : "l"(p));
    return v;
}

__global__ __launch_bounds__(256, 2)
void moe_gate_kernel(const float* __restrict__ x,
                     const float* __restrict__ wg,
                     const float* __restrict__ wn,
                     const float* __restrict__ noise,
                     float* __restrict__ out)
{
    const int lane   = threadIdx.x & 31;
    const int gwarp  = (blockIdx.x * blockDim.x + threadIdx.x) >> 5;
    const int nwarps = (gridDim.x * blockDim.x) >> 5;
    const int stride = 4 * nwarps;

    // Lane owns 8 CONTIGUOUS dims {8l..8l+7} -> 4 f32x2 dim-pairs.
    ull wgp[4][3], wnp[4][3];
#pragma unroll
    for (int p = 0; p < 4; ++p) {
        const int d = 8 * lane + 2 * p;
#pragma unroll
        for (int e = 0; e < 3; ++e) {
            wgp[p][e] = pk2(__ldg(wg + d * 3 + e), __ldg(wg + (d + 1) * 3 + e));
            wnp[p][e] = pk2(__ldg(wn + d * 3 + e), __ldg(wn + (d + 1) * 3 + e));
        }
    }

    // Row = 1024B; lane reads 32B at byte offset 32*lane (dims 8l..8l+7).
    const char* __restrict__ xb8 = (const char*)x;
    const unsigned loff = 32u * lane;

    const int quad  = lane >> 3;   // token this lane finalizes
    const int j     = lane & 7;    // role in quadrant (j<3 -> expert j)
    const int qbase = lane & 24;   // first lane of my quadrant
    const bool lo16 = (lane < 16);
    const bool lo8  = ((lane & 8) == 0);

    int t0 = 4 * gwarp;
    if (t0 >= GATE_N) return;

    // ---- prologue loads: 4x LDG.256 ----
    u64x4 xr[4];
#pragma unroll
    for (int q = 0; q < 4; ++q)
        xr[q] = ldg_stream256(xb8 + ((size_t)(t0 + q) << 10) + loff);
    float nsraw = (lane < 12) ? __ldg(noise + (size_t)t0 * 3 + lane) : 0.f;

    while (t0 < GATE_N) {
        const int tn = t0 + stride;

        // ---- FMA phase: per token 24 fma2, then unpack ----
        float P[4][6];
#pragma unroll
        for (int q = 0; q < 4; ++q) {
            ull a0 = 0, a1 = 0, a2 = 0, a3 = 0, a4 = 0, a5 = 0;
            const ull xp[4] = {xr[q].a, xr[q].b, xr[q].c, xr[q].d};
#pragma unroll
            for (int p = 0; p < 4; ++p) {
                fma2(a0, xp[p], wgp[p][0]);
                fma2(a1, xp[p], wgp[p][1]);
                fma2(a2, xp[p], wgp[p][2]);
                fma2(a3, xp[p], wnp[p][0]);
                fma2(a4, xp[p], wnp[p][1]);
                fma2(a5, xp[p], wnp[p][2]);
            }
            P[q][0] = unpk_sum(a0); P[q][1] = unpk_sum(a1); P[q][2] = unpk_sum(a2);
            P[q][3] = unpk_sum(a3); P[q][4] = unpk_sum(a4); P[q][5] = unpk_sum(a5);
        }

        // ---- prefetch next iteration (overlaps reduction + tail) ----
        float nsn = 0.f;
        if (tn < GATE_N) {
#pragma unroll
            for (int q = 0; q < 4; ++q)
                xr[q] = ldg_stream256(xb8 + ((size_t)(tn + q) << 10) + loff);
            if (lane < 12) nsn = __ldg(noise + (size_t)tn * 3 + lane);
        }

        // ---- fold round 1 (xor 16): T0<->T2, T1<->T3 ----
        float U[6], W[6];
#pragma unroll
        for (int e = 0; e < 6; ++e) {
            const float u  = lo16 ? P[0][e] : P[2][e];
            const float uv = lo16 ? P[2][e] : P[0][e];
            U[e] = u + __shfl_xor_sync(0xFFFFFFFFu, uv, 16);
            const float w  = lo16 ? P[1][e] : P[3][e];
            const float wv = lo16 ? P[3][e] : P[1][e];
            W[e] = w + __shfl_xor_sync(0xFFFFFFFFu, wv, 16);
        }

        // ---- fold round 2 (xor 8): quadrant q holds token q ----
        float R[6];
#pragma unroll
        for (int e = 0; e < 6; ++e) {
            const float r  = lo8 ? U[e] : W[e];
            const float rv = lo8 ? W[e] : U[e];
            R[e] = r + __shfl_xor_sync(0xFFFFFFFFu, rv, 8);
        }

        // ---- butterfly within 8-lane quadrants ----
#pragma unroll
        for (int off = 4; off > 0; off >>= 1) {
#pragma unroll
            for (int e = 0; e < 6; ++e)
                R[e] += __shfl_xor_sync(0xFFFFFFFFu, R[e], off);
        }

        // ---- tail: lane 8q+j (j<3) owns expert j of token q ----
        const float nv = __shfl_sync(0xFFFFFFFFu, nsraw, 3 * quad + j);
        const float cg = (j == 1) ? R[1] : ((j == 2) ? R[2] : R[0]);
        const float cn = (j == 1) ? R[4] : ((j == 2) ? R[5] : R[3]);
        const float sp = fmaxf(cn, 0.f) + log1pf(expf(-fabsf(cn)));
        const float logit = fmaf(nv, sp + NOISE_EPS, cg);

        const float l1 = __shfl_sync(0xFFFFFFFFu, logit, qbase + 1);
        const float l2 = __shfl_sync(0xFFFFFFFFu, logit, qbase + 2);

        if (j == 0) {
            int   idx  = 0;
            float best = logit;          // expert 0
            if (l1 > best) { best = l1; idx = 1; }
            if (l2 > best) {            idx = 2; }
            out[t0 + quad] = (float)idx; // 4 lanes, 16B coalesced
        }

        // ---- rotate pipeline ----
        nsraw = nsn;
        t0 = tn;
    }
}

extern "C" void kernel_launch(void* const* d_in, const int* in_sizes, int n_in,
                              void* d_out, int out_size)
{
    // Resolve inputs BY SIZE (robust to metadata ordering).
    //   N*D -> input, N*E -> noise, D*E -> w_gate (first), w_noise (second)
    const float* x   = nullptr;
    const float* wg  = nullptr;
    const float* wn  = nullptr;
    const float* nse = nullptr;

    for (int i = 0; i < n_in; ++i) {
        const long long sz = in_sizes[i];
        if (sz == (long long)GATE_N * GATE_D) {
            x = (const float*)d_in[i];
        } else if (sz == (long long)GATE_N * GATE_E) {
            nse = (const float*)d_in[i];
        } else if (sz == (long long)GATE_D * GATE_E) {
            if (!wg) wg = (const float*)d_in[i];
            else     wn = (const float*)d_in[i];
        }
    }

    float* out = (float*)d_out;
    (void)out_size;

    // 296 blocks = 148 SMs x 2 resident CTAs: one persistent wave.
    moe_gate_kernel<<<296, 256>>>(x, wg, wn, nse, out);
}